// round 1
// baseline (speedup 1.0000x reference)
#include <cuda_runtime.h>
#include <cstdint>

#define EDIM 1024
#define BDIM 1024
#define G4   4096          // 4*EDIM
#define MAXT 16
#define OUTD 34

// ---------------- device scratch (no allocations allowed) ----------------
__device__ float g_Wsum[G4 * EDIM];          // W_ih + W_hh   (16 MB)
__device__ float g_bsum[G4];                 // b_ih + b_hh
__device__ float g_h[BDIM * EDIM];           // hidden state  (4 MB)
__device__ float g_c[BDIM * EDIM];           // cell state    (4 MB)
__device__ float g_gates[BDIM * G4];         // gate pre-activations (16 MB)
__device__ float g_hseq[MAXT * BDIM * EDIM]; // h history     (64 MB)

// ---------------- f32x2 packed helpers (sm_100+ PTX) ----------------
__device__ __forceinline__ unsigned long long pk2(float lo, float hi) {
    unsigned long long r;
    asm("mov.b64 %0, {%1, %2};" : "=l"(r) : "f"(lo), "f"(hi));
    return r;
}
__device__ __forceinline__ void ffma2(unsigned long long& d,
                                      unsigned long long a,
                                      unsigned long long b) {
    asm("fma.rn.f32x2 %0, %1, %2, %3;" : "=l"(d) : "l"(a), "l"(b), "l"(d));
}
__device__ __forceinline__ float2 upk2(unsigned long long v) {
    float2 r;
    asm("mov.b64 {%0, %1}, %2;" : "=f"(r.x), "=f"(r.y) : "l"(v));
    return r;
}

// ---------------- prep: W_sum, b_sum, copy h/c into state ----------------
__global__ void prep_kernel(const float* __restrict__ W_ih,
                            const float* __restrict__ W_hh,
                            const float* __restrict__ b_ih,
                            const float* __restrict__ b_hh,
                            const float* __restrict__ h0,
                            const float* __restrict__ c0) {
    int i = blockIdx.x * blockDim.x + threadIdx.x;   // float4 index
    const int NW4 = (G4 * EDIM) / 4;                 // 1048576
    if (i < NW4) {
        float4 a = reinterpret_cast<const float4*>(W_ih)[i];
        float4 b = reinterpret_cast<const float4*>(W_hh)[i];
        float4 r = make_float4(a.x + b.x, a.y + b.y, a.z + b.z, a.w + b.w);
        reinterpret_cast<float4*>(g_Wsum)[i] = r;
    }
    if (i < (BDIM * EDIM) / 4) {
        reinterpret_cast<float4*>(g_h)[i] = reinterpret_cast<const float4*>(h0)[i];
        reinterpret_cast<float4*>(g_c)[i] = reinterpret_cast<const float4*>(c0)[i];
    }
    if (i < G4 / 4) {
        float4 a = reinterpret_cast<const float4*>(b_ih)[i];
        float4 b = reinterpret_cast<const float4*>(b_hh)[i];
        float4 r = make_float4(a.x + b.x, a.y + b.y, a.z + b.z, a.w + b.w);
        reinterpret_cast<float4*>(g_bsum)[i] = r;
    }
}

// ---------------- GEMM: gates[B,4096] = h[B,1024] @ W[4096,1024]^T + bsum --
// 128x128 block tile, BK=16, 8x8 microtile per thread, f32x2 accumulation.
__global__ __launch_bounds__(256)
void gemm_gates(const float* __restrict__ Wext, int use_sum) {
    const float* __restrict__ W = use_sum ? g_Wsum : Wext;

    __shared__ float As[16][128];   // k-major A tile
    __shared__ float Bs[16][128];   // k-major W tile

    const int tid = threadIdx.x;
    const int n0 = blockIdx.x * 128;
    const int m0 = blockIdx.y * 128;
    const int tx = tid & 15;        // N direction
    const int ty = tid >> 4;        // M direction
    const int rm = ty * 8;
    const int cn = tx * 8;

    // loader mapping: 512 float4 per tile per matrix, 2 per thread
    const int lrow = tid >> 2;      // 0..63 ; second load covers +64
    const int lq   = tid & 3;       // which float4 within the 16-wide k row

    const float* Aptr  = g_h + (size_t)(m0 + lrow) * EDIM + lq * 4;
    const float* Aptr2 = Aptr + (size_t)64 * EDIM;
    const float* Wptr  = W + (size_t)(n0 + lrow) * EDIM + lq * 4;
    const float* Wptr2 = Wptr + (size_t)64 * EDIM;

    unsigned long long acc[8][4];
#pragma unroll
    for (int i = 0; i < 8; ++i)
#pragma unroll
        for (int j = 0; j < 4; ++j) acc[i][j] = 0ULL;

    // prefetch chunk 0
    float4 ar0 = *reinterpret_cast<const float4*>(Aptr);
    float4 ar1 = *reinterpret_cast<const float4*>(Aptr2);
    float4 br0 = *reinterpret_cast<const float4*>(Wptr);
    float4 br1 = *reinterpret_cast<const float4*>(Wptr2);

    const int NKT = EDIM / 16;      // 64 k-chunks
    for (int kt = 0; kt < NKT; ++kt) {
        __syncthreads();            // previous compute done before overwrite
        const int kb = lq * 4;
        As[kb + 0][lrow] = ar0.x; As[kb + 1][lrow] = ar0.y;
        As[kb + 2][lrow] = ar0.z; As[kb + 3][lrow] = ar0.w;
        As[kb + 0][lrow + 64] = ar1.x; As[kb + 1][lrow + 64] = ar1.y;
        As[kb + 2][lrow + 64] = ar1.z; As[kb + 3][lrow + 64] = ar1.w;
        Bs[kb + 0][lrow] = br0.x; Bs[kb + 1][lrow] = br0.y;
        Bs[kb + 2][lrow] = br0.z; Bs[kb + 3][lrow] = br0.w;
        Bs[kb + 0][lrow + 64] = br1.x; Bs[kb + 1][lrow + 64] = br1.y;
        Bs[kb + 2][lrow + 64] = br1.z; Bs[kb + 3][lrow + 64] = br1.w;
        __syncthreads();

        if (kt + 1 < NKT) {         // prefetch next chunk (overlaps compute)
            int off = (kt + 1) * 16;
            ar0 = *reinterpret_cast<const float4*>(Aptr  + off);
            ar1 = *reinterpret_cast<const float4*>(Aptr2 + off);
            br0 = *reinterpret_cast<const float4*>(Wptr  + off);
            br1 = *reinterpret_cast<const float4*>(Wptr2 + off);
        }

#pragma unroll
        for (int kk = 0; kk < 16; ++kk) {
            float4 a0 = *reinterpret_cast<const float4*>(&As[kk][rm]);
            float4 a1 = *reinterpret_cast<const float4*>(&As[kk][rm + 4]);
            float4 b0 = *reinterpret_cast<const float4*>(&Bs[kk][cn]);
            float4 b1 = *reinterpret_cast<const float4*>(&Bs[kk][cn + 4]);
            unsigned long long Bp0 = pk2(b0.x, b0.y);
            unsigned long long Bp1 = pk2(b0.z, b0.w);
            unsigned long long Bp2 = pk2(b1.x, b1.y);
            unsigned long long Bp3 = pk2(b1.z, b1.w);
            float av[8] = {a0.x, a0.y, a0.z, a0.w, a1.x, a1.y, a1.z, a1.w};
#pragma unroll
            for (int i = 0; i < 8; ++i) {
                unsigned long long Ad = pk2(av[i], av[i]);
                ffma2(acc[i][0], Ad, Bp0);
                ffma2(acc[i][1], Ad, Bp1);
                ffma2(acc[i][2], Ad, Bp2);
                ffma2(acc[i][3], Ad, Bp3);
            }
        }
    }

    // epilogue: unpack, add fused bias, store
    float bias[8];
#pragma unroll
    for (int j = 0; j < 8; ++j) bias[j] = g_bsum[n0 + cn + j];
#pragma unroll
    for (int i = 0; i < 8; ++i) {
        float* crow = g_gates + (size_t)(m0 + rm + i) * G4 + n0 + cn;
#pragma unroll
        for (int j2 = 0; j2 < 4; ++j2) {
            float2 v = upk2(acc[i][j2]);
            crow[2 * j2 + 0] = v.x + bias[2 * j2 + 0];
            crow[2 * j2 + 1] = v.y + bias[2 * j2 + 1];
        }
    }
}

// ---------------- elementwise LSTM cell update ----------------
__global__ void lstm_update(int t) {
    int idx = blockIdx.x * blockDim.x + threadIdx.x;   // < B*E
    int b = idx >> 10;
    int e = idx & 1023;
    size_t gb = (size_t)b * G4 + e;
    float xi = g_gates[gb];
    float xf = g_gates[gb + EDIM];
    float xg = g_gates[gb + 2 * EDIM];
    float xo = g_gates[gb + 3 * EDIM];
    float iv = 1.f / (1.f + expf(-xi));
    float fv = 1.f / (1.f + expf(-xf));
    float gv = tanhf(xg);
    float ov = 1.f / (1.f + expf(-xo));
    float cv = fv * g_c[idx] + iv * gv;
    float hv = ov * tanhf(cv);
    g_c[idx] = cv;
    g_h[idx] = hv;
    g_hseq[(size_t)t * (BDIM * EDIM) + idx] = hv;
}

// ---------------- output projection: out[b,t,o] = hseq[t,b,:]·W_out[o,:]+b_out
__global__ void out_proj(const float* __restrict__ W_out,
                         const float* __restrict__ b_out,
                         float* __restrict__ out, int T) {
    int id = blockIdx.x * blockDim.x + threadIdx.x;
    if (id >= BDIM * T * OUTD) return;
    int o  = id % OUTD;
    int bt = id / OUTD;
    int t  = bt % T;
    int b  = bt / T;
    const float4* hv = reinterpret_cast<const float4*>(g_hseq + ((size_t)t * BDIM + b) * EDIM);
    const float4* wv = reinterpret_cast<const float4*>(W_out + (size_t)o * EDIM);
    float s = 0.f;
#pragma unroll 4
    for (int k = 0; k < EDIM / 4; ++k) {
        float4 a = hv[k];
        float4 w = wv[k];
        s += a.x * w.x + a.y * w.y + a.z * w.z + a.w * w.w;
    }
    out[id] = s + b_out[o];   // id == (b*T + t)*OUTD + o
}

// ---------------- launch ----------------
extern "C" void kernel_launch(void* const* d_in, const int* in_sizes, int n_in,
                              void* d_out, int out_size) {
    const float* h    = (const float*)d_in[0];
    const float* c    = (const float*)d_in[1];
    const float* W_ih = (const float*)d_in[2];
    const float* W_hh = (const float*)d_in[3];
    const float* b_ih = (const float*)d_in[4];
    const float* b_hh = (const float*)d_in[5];
    const float* W_out = (const float*)d_in[6];
    const float* b_out = (const float*)d_in[7];
    float* out = (float*)d_out;

    int T = out_size / (BDIM * OUTD);   // = future_preds (10)
    if (T < 1) T = 1;
    if (T > MAXT) T = MAXT;

    prep_kernel<<<(G4 * EDIM / 4 + 255) / 256, 256>>>(W_ih, W_hh, b_ih, b_hh, h, c);

    dim3 ggrid(G4 / 128, BDIM / 128);   // (32, 8)
    for (int t = 0; t < T; ++t) {
        gemm_gates<<<ggrid, 256>>>(W_hh, t > 0 ? 1 : 0);
        lstm_update<<<(BDIM * EDIM) / 256, 256>>>(t);
    }
    out_proj<<<(BDIM * T * OUTD + 127) / 128, 128>>>(W_out, b_out, out, T);
}

// round 4
// speedup vs baseline: 2.7618x; 2.7618x over previous
#include <cuda_runtime.h>
#include <cuda_bf16.h>
#include <cstdint>

#define EDIM 1024
#define BDIM 1024
#define G4   4096
#define MAXT 16
#define OUTD 34

#define BM 128
#define BN 128
#define BK 64
#define NCK (EDIM / BK)        // 16 k-chunks
#define NTHREADS 256

#define STAGEB 65536           // Ahi16K + Alo16K + Bhi16K + Blo16K
#define AHI 0
#define ALO 16384
#define BHI 32768
#define BLO 49152
#define SMEM_LSTM (1024 + 3 * STAGEB)   // bias area + 3 stages = 197632

#define HSZ (BDIM * EDIM)

// ----------------- device scratch -----------------
__device__ __nv_bfloat16 g_Ws_hi[G4 * EDIM];
__device__ __nv_bfloat16 g_Ws_lo[G4 * EDIM];
__device__ __nv_bfloat16 g_Wh_hi[G4 * EDIM];
__device__ __nv_bfloat16 g_Wh_lo[G4 * EDIM];
__device__ float         g_bsum_p[G4];
// ping-pong h buffers: step t reads parity t&1, writes parity (t+1)&1.
__device__ __nv_bfloat16 g_hhi[2 * HSZ];
__device__ __nv_bfloat16 g_hlo[2 * HSZ];
__device__ float         g_c[HSZ];
__device__ float         g_hseq[MAXT * HSZ];

// ----------------- helpers -----------------
__device__ __forceinline__ uint32_t smem_u32(const void* p) {
    uint32_t a;
    asm("{ .reg .u64 t; cvta.to.shared.u64 t, %1; cvt.u32.u64 %0, t; }" : "=r"(a) : "l"(p));
    return a;
}
__device__ __forceinline__ void cpa16(uint32_t dst, const void* src) {
    asm volatile("cp.async.cg.shared.global [%0], [%1], 16;" :: "r"(dst), "l"(src));
}
__device__ __forceinline__ void cpa_commit() {
    asm volatile("cp.async.commit_group;" ::: "memory");
}
__device__ __forceinline__ void ldsm4(uint32_t* r, uint32_t a) {
    asm volatile("ldmatrix.sync.aligned.m8n8.x4.shared.b16 {%0,%1,%2,%3}, [%4];"
                 : "=r"(r[0]), "=r"(r[1]), "=r"(r[2]), "=r"(r[3]) : "r"(a));
}
__device__ __forceinline__ void mma16816(float& d0, float& d1, float& d2, float& d3,
                                         uint32_t a0, uint32_t a1, uint32_t a2, uint32_t a3,
                                         uint32_t b0, uint32_t b1) {
    asm volatile("mma.sync.aligned.m16n8k16.row.col.f32.bf16.bf16.f32 "
                 "{%0,%1,%2,%3}, {%4,%5,%6,%7}, {%8,%9}, {%0,%1,%2,%3};"
                 : "+f"(d0), "+f"(d1), "+f"(d2), "+f"(d3)
                 : "r"(a0), "r"(a1), "r"(a2), "r"(a3), "r"(b0), "r"(b1));
}
__device__ __forceinline__ float fsig(float x) {
    float t = __expf(-x);
    return __fdividef(1.f, 1.f + t);
}
__device__ __forceinline__ float ftanh_(float x) {
    float t = __expf(-2.f * x);
    return __fdividef(1.f - t, 1.f + t);
}
__device__ __forceinline__ void bsplit(float v, unsigned short& h, unsigned short& l) {
    __nv_bfloat16 hb = __float2bfloat16(v);
    float r = v - __bfloat162float(hb);
    __nv_bfloat16 lb = __float2bfloat16(r);
    h = __bfloat16_as_ushort(hb);
    l = __bfloat16_as_ushort(lb);
}

// permutation: original W row r = g*1024 + e  ->  rp = (e>>5)*128 + g*32 + (e&31)
// so N-block nb (128 rows) holds e in [nb*32, nb*32+32) for all 4 gates.

// ----------------- prep kernels -----------------
__global__ void prep_w(const float* __restrict__ Wih, const float* __restrict__ Whh) {
    int id = blockIdx.x * 256 + threadIdx.x;     // row * 256 float4 quads
    int r = id >> 8;
    int q = id & 255;
    float4 a = reinterpret_cast<const float4*>(Wih)[(size_t)r * 256 + q];
    float4 b = reinterpret_cast<const float4*>(Whh)[(size_t)r * 256 + q];
    int g = r >> 10, e = r & 1023;
    int rp = ((e >> 5) << 7) + (g << 5) + (e & 31);
    size_t o = (size_t)rp * 256 + q;

    ushort4 hh, hl, sh, sl;
    bsplit(b.x, hh.x, hl.x); bsplit(b.y, hh.y, hl.y);
    bsplit(b.z, hh.z, hl.z); bsplit(b.w, hh.w, hl.w);
    float4 s = make_float4(a.x + b.x, a.y + b.y, a.z + b.z, a.w + b.w);
    bsplit(s.x, sh.x, sl.x); bsplit(s.y, sh.y, sl.y);
    bsplit(s.z, sh.z, sl.z); bsplit(s.w, sh.w, sl.w);

    reinterpret_cast<ushort4*>(g_Wh_hi)[o] = hh;
    reinterpret_cast<ushort4*>(g_Wh_lo)[o] = hl;
    reinterpret_cast<ushort4*>(g_Ws_hi)[o] = sh;
    reinterpret_cast<ushort4*>(g_Ws_lo)[o] = sl;
}

__global__ void prep_state(const float* __restrict__ h0, const float* __restrict__ c0,
                           const float* __restrict__ bih, const float* __restrict__ bhh) {
    int id = blockIdx.x * 256 + threadIdx.x;     // float4 index over B*E/4
    float4 hv = reinterpret_cast<const float4*>(h0)[id];
    ushort4 hh, hl;
    bsplit(hv.x, hh.x, hl.x); bsplit(hv.y, hh.y, hl.y);
    bsplit(hv.z, hh.z, hl.z); bsplit(hv.w, hh.w, hl.w);
    reinterpret_cast<ushort4*>(g_hhi)[id] = hh;   // parity-0 buffer
    reinterpret_cast<ushort4*>(g_hlo)[id] = hl;
    reinterpret_cast<float4*>(g_c)[id] = reinterpret_cast<const float4*>(c0)[id];
    if (id < G4) {
        int g = id >> 10, e = id & 1023;
        int rp = ((e >> 5) << 7) + (g << 5) + (e & 31);
        g_bsum_p[rp] = bih[id] + bhh[id];
    }
}

// ----------------- fused GEMM (mma.sync bf16 3-term) + LSTM update -----------------
__global__ __launch_bounds__(NTHREADS, 1)
void lstm_step(int use_sum, int t) {
    extern __shared__ char smem[];
    float* bias_sm = reinterpret_cast<float*>(smem);
    const uint32_t sbase = smem_u32(smem) + 1024;
    const int tid = threadIdx.x;
    const int lane = tid & 31;
    const int w = tid >> 5;
    const int nb = blockIdx.x;     // 0..31
    const int mb = blockIdx.y;     // 0..7
    const int m0 = mb * BM, n0 = nb * BN;

    // ping-pong: read parity t&1, write parity (t+1)&1
    const __nv_bfloat16* __restrict__ hin_hi = g_hhi + (size_t)(t & 1) * HSZ;
    const __nv_bfloat16* __restrict__ hin_lo = g_hlo + (size_t)(t & 1) * HSZ;
    __nv_bfloat16* __restrict__ hout_hi = g_hhi + (size_t)((t + 1) & 1) * HSZ;
    __nv_bfloat16* __restrict__ hout_lo = g_hlo + (size_t)((t + 1) & 1) * HSZ;

    const __nv_bfloat16* __restrict__ Bh = use_sum ? g_Ws_hi : g_Wh_hi;
    const __nv_bfloat16* __restrict__ Bl = use_sum ? g_Ws_lo : g_Wh_lo;

    if (tid < BN) bias_sm[tid] = g_bsum_p[n0 + tid];

    // ---- loaders: 16 cp.async per thread per stage ----
    const int lrow = tid >> 3;     // 0..31
    const int lq = tid & 7;

#define LOAD_STAGE(s, kc)                                                          \
    {                                                                              \
        uint32_t sb = sbase + (s) * STAGEB;                                        \
        size_t gc = (size_t)(kc) * 64 + lq * 8;                                    \
        _Pragma("unroll")                                                          \
        for (int i = 0; i < 4; ++i) {                                              \
            int row = lrow + i * 32;                                               \
            uint32_t sf = (uint32_t)row * 128 + (((lq ^ (row & 7)) << 4));         \
            cpa16(sb + AHI + sf, hin_hi + (size_t)(m0 + row) * EDIM + gc);         \
            cpa16(sb + ALO + sf, hin_lo + (size_t)(m0 + row) * EDIM + gc);         \
            cpa16(sb + BHI + sf, Bh + (size_t)(n0 + row) * EDIM + gc);             \
            cpa16(sb + BLO + sf, Bl + (size_t)(n0 + row) * EDIM + gc);             \
        }                                                                          \
        cpa_commit();                                                              \
    }

    float acc[16][4];
#pragma unroll
    for (int i = 0; i < 16; ++i)
#pragma unroll
        for (int j = 0; j < 4; ++j) acc[i][j] = 0.f;

    // ldmatrix lane geometry
    const int ar = w * 16 + (lane & 7) + ((lane >> 3) & 1) * 8;  // A row
    const int adq = lane >> 4;                                   // A k-quad offset
    const int bn = (lane & 7) + ((lane >> 4) << 3);              // B n within pair
    const int bdq = (lane >> 3) & 1;                             // B k-quad offset

    LOAD_STAGE(0, 0)
    LOAD_STAGE(1, 1)

    for (int kc = 0; kc < NCK; ++kc) {
        if (kc == NCK - 1)
            asm volatile("cp.async.wait_group 0;" ::: "memory");
        else
            asm volatile("cp.async.wait_group 1;" ::: "memory");
        __syncthreads();
        if (kc + 2 < NCK) {
            int s2 = (kc + 2) % 3;
            LOAD_STAGE(s2, kc + 2)
        }
        uint32_t sb = sbase + (kc % 3) * STAGEB;
#pragma unroll
        for (int k16 = 0; k16 < 4; ++k16) {
            int qa = k16 * 2 + adq;
            uint32_t aoff = (uint32_t)ar * 128 + ((qa ^ (ar & 7)) << 4);
            uint32_t ah[4], al[4];
            ldsm4(ah, sb + AHI + aoff);
            ldsm4(al, sb + ALO + aoff);
            int qb = k16 * 2 + bdq;
#pragma unroll
            for (int np = 0; np < 8; ++np) {
                int n = np * 16 + bn;
                uint32_t boff = (uint32_t)n * 128 + ((qb ^ (n & 7)) << 4);
                uint32_t bh[4], bl[4];
                ldsm4(bh, sb + BHI + boff);
                ldsm4(bl, sb + BLO + boff);
                mma16816(acc[2*np][0], acc[2*np][1], acc[2*np][2], acc[2*np][3],
                         ah[0], ah[1], ah[2], ah[3], bh[0], bh[1]);
                mma16816(acc[2*np][0], acc[2*np][1], acc[2*np][2], acc[2*np][3],
                         ah[0], ah[1], ah[2], ah[3], bl[0], bl[1]);
                mma16816(acc[2*np][0], acc[2*np][1], acc[2*np][2], acc[2*np][3],
                         al[0], al[1], al[2], al[3], bh[0], bh[1]);
                mma16816(acc[2*np+1][0], acc[2*np+1][1], acc[2*np+1][2], acc[2*np+1][3],
                         ah[0], ah[1], ah[2], ah[3], bh[2], bh[3]);
                mma16816(acc[2*np+1][0], acc[2*np+1][1], acc[2*np+1][2], acc[2*np+1][3],
                         ah[0], ah[1], ah[2], ah[3], bl[2], bl[3]);
                mma16816(acc[2*np+1][0], acc[2*np+1][1], acc[2*np+1][2], acc[2*np+1][3],
                         al[0], al[1], al[2], al[3], bh[2], bh[3]);
            }
        }
    }

    // ---- fused epilogue: per-thread register LSTM update ----
    const int mrb = m0 + w * 16 + (lane >> 2);
    const int cp = (lane & 3) * 2;
    float* hseq = g_hseq + (size_t)t * HSZ;
#pragma unroll
    for (int q = 0; q < 4; ++q) {
#pragma unroll
        for (int rr = 0; rr < 2; ++rr) {
            int m = mrb + rr * 8;
            int nloc = q * 8 + cp;
            float xi0 = acc[q][rr*2+0]      + bias_sm[nloc];
            float xi1 = acc[q][rr*2+1]      + bias_sm[nloc + 1];
            float xf0 = acc[4+q][rr*2+0]    + bias_sm[32 + nloc];
            float xf1 = acc[4+q][rr*2+1]    + bias_sm[32 + nloc + 1];
            float xg0 = acc[8+q][rr*2+0]    + bias_sm[64 + nloc];
            float xg1 = acc[8+q][rr*2+1]    + bias_sm[64 + nloc + 1];
            float xo0 = acc[12+q][rr*2+0]   + bias_sm[96 + nloc];
            float xo1 = acc[12+q][rr*2+1]   + bias_sm[96 + nloc + 1];
            size_t off = (size_t)m * EDIM + nb * 32 + nloc;
            float2 cold = *reinterpret_cast<const float2*>(g_c + off);
            float cn0 = fsig(xf0) * cold.x + fsig(xi0) * ftanh_(xg0);
            float cn1 = fsig(xf1) * cold.y + fsig(xi1) * ftanh_(xg1);
            float hn0 = fsig(xo0) * ftanh_(cn0);
            float hn1 = fsig(xo1) * ftanh_(cn1);
            *reinterpret_cast<float2*>(g_c + off) = make_float2(cn0, cn1);
            *reinterpret_cast<float2*>(hseq + off) = make_float2(hn0, hn1);
            unsigned short h0, l0, h1, l1;
            bsplit(hn0, h0, l0);
            bsplit(hn1, h1, l1);
            *reinterpret_cast<uint32_t*>(reinterpret_cast<unsigned short*>(hout_hi) + off) =
                (uint32_t)h0 | ((uint32_t)h1 << 16);
            *reinterpret_cast<uint32_t*>(reinterpret_cast<unsigned short*>(hout_lo) + off) =
                (uint32_t)l0 | ((uint32_t)l1 << 16);
        }
    }
}

// ----------------- output projection -----------------
#define OPR 16
#define OPSTRIDE 1040
__global__ void out_proj(const float* __restrict__ Wo, const float* __restrict__ bo,
                         float* __restrict__ out, int T) {
    extern __shared__ float hs[];   // OPR rows, stride OPSTRIDE
    int t = blockIdx.y;
    int b0 = blockIdx.x * OPR;
    int tid = threadIdx.y * 17 + threadIdx.x;   // 136 threads
    const float4* src = reinterpret_cast<const float4*>(g_hseq + ((size_t)t * BDIM + b0) * EDIM);
    for (int i = tid; i < OPR * 256; i += 136) {
        int r = i >> 8, c = i & 255;
        reinterpret_cast<float4*>(hs + r * OPSTRIDE)[c] = src[(size_t)r * 256 + c];
    }
    __syncthreads();
    int o0 = threadIdx.x * 2, o1 = o0 + 1;
    int r0 = threadIdx.y * 2, r1 = r0 + 1;
    const float4* w0 = reinterpret_cast<const float4*>(Wo + (size_t)o0 * EDIM);
    const float4* w1 = reinterpret_cast<const float4*>(Wo + (size_t)o1 * EDIM);
    const float4* h0 = reinterpret_cast<const float4*>(hs + r0 * OPSTRIDE);
    const float4* h1 = reinterpret_cast<const float4*>(hs + r1 * OPSTRIDE);
    float s00 = 0.f, s01 = 0.f, s10 = 0.f, s11 = 0.f;
#pragma unroll 4
    for (int k = 0; k < 256; ++k) {
        float4 a = h0[k], b = h1[k], x = w0[k], y = w1[k];
        s00 += a.x * x.x + a.y * x.y + a.z * x.z + a.w * x.w;
        s01 += a.x * y.x + a.y * y.y + a.z * y.z + a.w * y.w;
        s10 += b.x * x.x + b.y * x.y + b.z * x.z + b.w * x.w;
        s11 += b.x * y.x + b.y * y.y + b.z * y.z + b.w * y.w;
    }
    float bb0 = bo[o0], bb1 = bo[o1];
    size_t ob = ((size_t)(b0 + r0) * T + t) * OUTD;
    out[ob + o0] = s00 + bb0;
    out[ob + o1] = s01 + bb1;
    ob = ((size_t)(b0 + r1) * T + t) * OUTD;
    out[ob + o0] = s10 + bb0;
    out[ob + o1] = s11 + bb1;
}

// ----------------- launch -----------------
extern "C" void kernel_launch(void* const* d_in, const int* in_sizes, int n_in,
                              void* d_out, int out_size) {
    const float* h     = (const float*)d_in[0];
    const float* c     = (const float*)d_in[1];
    const float* W_ih  = (const float*)d_in[2];
    const float* W_hh  = (const float*)d_in[3];
    const float* b_ih  = (const float*)d_in[4];
    const float* b_hh  = (const float*)d_in[5];
    const float* W_out = (const float*)d_in[6];
    const float* b_out = (const float*)d_in[7];
    float* out = (float*)d_out;

    int T = out_size / (BDIM * OUTD);
    if (T < 1) T = 1;
    if (T > MAXT) T = MAXT;

    cudaFuncSetAttribute(lstm_step, cudaFuncAttributeMaxDynamicSharedMemorySize, SMEM_LSTM);
    cudaFuncSetAttribute(out_proj, cudaFuncAttributeMaxDynamicSharedMemorySize,
                         OPR * OPSTRIDE * 4);

    prep_w<<<G4, 256>>>(W_ih, W_hh);
    prep_state<<<(BDIM * EDIM / 4) / 256, 256>>>(h, c, b_ih, b_hh);

    dim3 grid(G4 / BN, BDIM / BM);   // (32, 8) = 256 CTAs
    for (int t = 0; t < T; ++t)
        lstm_step<<<grid, NTHREADS, SMEM_LSTM>>>(t > 0 ? 1 : 0, t);

    dim3 opgrid(BDIM / OPR, T);
    dim3 opblk(17, 8);
    out_proj<<<opgrid, opblk, OPR * OPSTRIDE * 4>>>(W_out, b_out, out, T);
}

// round 6
// speedup vs baseline: 3.0631x; 1.1091x over previous
#include <cuda_runtime.h>
#include <cuda_bf16.h>
#include <cstdint>

#define EDIM 1024
#define BDIM 1024
#define G4   4096
#define MAXT 16
#define OUTD 34

#define BM 128
#define BN 256
#define BK 64
#define NCK (EDIM / BK)        // 16 k-chunks
#define NTHREADS 256

#define STAGEB 98304           // Ahi16K + Alo16K + Bhi32K + Blo32K
#define AHI 0
#define ALO 16384
#define BHI 32768
#define BLO 65536
#define SMEM_LSTM (1024 + 2 * STAGEB)   // bias + 2 stages = 197632

#define HSZ (BDIM * EDIM)

// ----------------- device scratch -----------------
__device__ __nv_bfloat16 g_Ws_hi[G4 * EDIM];
__device__ __nv_bfloat16 g_Ws_lo[G4 * EDIM];
__device__ __nv_bfloat16 g_Wh_hi[G4 * EDIM];
__device__ __nv_bfloat16 g_Wh_lo[G4 * EDIM];
__device__ float         g_bsum_p[G4];
// ping-pong h buffers: step t reads parity t&1, writes parity (t+1)&1.
__device__ __nv_bfloat16 g_hhi[2 * HSZ];
__device__ __nv_bfloat16 g_hlo[2 * HSZ];
__device__ float         g_c[HSZ];
__device__ float         g_hseq[MAXT * HSZ];

// ----------------- helpers -----------------
__device__ __forceinline__ uint32_t smem_u32(const void* p) {
    uint32_t a;
    asm("{ .reg .u64 t; cvta.to.shared.u64 t, %1; cvt.u32.u64 %0, t; }" : "=r"(a) : "l"(p));
    return a;
}
__device__ __forceinline__ void cpa16(uint32_t dst, const void* src) {
    asm volatile("cp.async.cg.shared.global [%0], [%1], 16;" :: "r"(dst), "l"(src));
}
__device__ __forceinline__ void cpa_commit() {
    asm volatile("cp.async.commit_group;" ::: "memory");
}
__device__ __forceinline__ void ldsm4(uint32_t* r, uint32_t a) {
    asm volatile("ldmatrix.sync.aligned.m8n8.x4.shared.b16 {%0,%1,%2,%3}, [%4];"
                 : "=r"(r[0]), "=r"(r[1]), "=r"(r[2]), "=r"(r[3]) : "r"(a));
}
__device__ __forceinline__ void mma16816(float* d,
                                         const uint32_t* a,
                                         uint32_t b0, uint32_t b1) {
    asm volatile("mma.sync.aligned.m16n8k16.row.col.f32.bf16.bf16.f32 "
                 "{%0,%1,%2,%3}, {%4,%5,%6,%7}, {%8,%9}, {%0,%1,%2,%3};"
                 : "+f"(d[0]), "+f"(d[1]), "+f"(d[2]), "+f"(d[3])
                 : "r"(a[0]), "r"(a[1]), "r"(a[2]), "r"(a[3]), "r"(b0), "r"(b1));
}
__device__ __forceinline__ float fsig(float x) {
    float t = __expf(-x);
    return __fdividef(1.f, 1.f + t);
}
__device__ __forceinline__ float ftanh_(float x) {
    float t = __expf(-2.f * x);
    return __fdividef(1.f - t, 1.f + t);
}
__device__ __forceinline__ void bsplit(float v, unsigned short& h, unsigned short& l) {
    __nv_bfloat16 hb = __float2bfloat16(v);
    float r = v - __bfloat162float(hb);
    __nv_bfloat16 lb = __float2bfloat16(r);
    h = __bfloat16_as_ushort(hb);
    l = __bfloat16_as_ushort(lb);
}

// permutation: original W row r = g*1024 + e  ->  rp = (e>>6)*256 + g*64 + (e&63)
// so N-block nb (256 rows) holds e in [nb*64, nb*64+64) for all 4 gates,
// gate g at local rows [g*64, g*64+64).

// ----------------- prep kernels -----------------
__global__ void prep_w(const float* __restrict__ Wih, const float* __restrict__ Whh) {
    int id = blockIdx.x * 256 + threadIdx.x;     // row * 256 float4 quads
    int r = id >> 8;
    int q = id & 255;
    float4 a = reinterpret_cast<const float4*>(Wih)[(size_t)r * 256 + q];
    float4 b = reinterpret_cast<const float4*>(Whh)[(size_t)r * 256 + q];
    int g = r >> 10, e = r & 1023;
    int rp = ((e >> 6) << 8) + (g << 6) + (e & 63);
    size_t o = (size_t)rp * 256 + q;

    ushort4 hh, hl, sh, sl;
    bsplit(b.x, hh.x, hl.x); bsplit(b.y, hh.y, hl.y);
    bsplit(b.z, hh.z, hl.z); bsplit(b.w, hh.w, hl.w);
    float4 s = make_float4(a.x + b.x, a.y + b.y, a.z + b.z, a.w + b.w);
    bsplit(s.x, sh.x, sl.x); bsplit(s.y, sh.y, sl.y);
    bsplit(s.z, sh.z, sl.z); bsplit(s.w, sh.w, sl.w);

    reinterpret_cast<ushort4*>(g_Wh_hi)[o] = hh;
    reinterpret_cast<ushort4*>(g_Wh_lo)[o] = hl;
    reinterpret_cast<ushort4*>(g_Ws_hi)[o] = sh;
    reinterpret_cast<ushort4*>(g_Ws_lo)[o] = sl;
}

__global__ void prep_state(const float* __restrict__ h0, const float* __restrict__ c0,
                           const float* __restrict__ bih, const float* __restrict__ bhh) {
    int id = blockIdx.x * 256 + threadIdx.x;     // float4 index over B*E/4
    float4 hv = reinterpret_cast<const float4*>(h0)[id];
    ushort4 hh, hl;
    bsplit(hv.x, hh.x, hl.x); bsplit(hv.y, hh.y, hl.y);
    bsplit(hv.z, hh.z, hl.z); bsplit(hv.w, hh.w, hl.w);
    reinterpret_cast<ushort4*>(g_hhi)[id] = hh;   // parity-0 buffer
    reinterpret_cast<ushort4*>(g_hlo)[id] = hl;
    reinterpret_cast<float4*>(g_c)[id] = reinterpret_cast<const float4*>(c0)[id];
    if (id < G4) {
        int g = id >> 10, e = id & 1023;
        int rp = ((e >> 6) << 8) + (g << 6) + (e & 63);
        g_bsum_p[rp] = bih[id] + bhh[id];
    }
}

// ----------------- fused GEMM (mma.sync bf16 3-term) + LSTM update -----------------
__global__ __launch_bounds__(NTHREADS, 1)
void lstm_step(int use_sum, int t) {
    extern __shared__ char smem[];
    float* bias_sm = reinterpret_cast<float*>(smem);
    const uint32_t sbase = smem_u32(smem) + 1024;
    const int tid = threadIdx.x;
    const int lane = tid & 31;
    const int w = tid >> 5;
    const int wr = w >> 2;         // 0..1   (m64 row)
    const int wc = w & 3;          // 0..3   (16-e column group)
    const int nb = blockIdx.x;     // 0..15
    const int mb = blockIdx.y;     // 0..7
    const int m0 = mb * BM, n0 = nb * BN;

    // ping-pong: read parity t&1, write parity (t+1)&1
    const __nv_bfloat16* __restrict__ hin_hi = g_hhi + (size_t)(t & 1) * HSZ;
    const __nv_bfloat16* __restrict__ hin_lo = g_hlo + (size_t)(t & 1) * HSZ;
    __nv_bfloat16* __restrict__ hout_hi = g_hhi + (size_t)((t + 1) & 1) * HSZ;
    __nv_bfloat16* __restrict__ hout_lo = g_hlo + (size_t)((t + 1) & 1) * HSZ;

    const __nv_bfloat16* __restrict__ Bh = use_sum ? g_Ws_hi : g_Wh_hi;
    const __nv_bfloat16* __restrict__ Bl = use_sum ? g_Ws_lo : g_Wh_lo;

    if (tid < BN) bias_sm[tid] = g_bsum_p[n0 + tid];

    // ---- loaders: 24 cp.async per thread per stage ----
    const int lrow = tid >> 3;     // 0..31
    const int lq = tid & 7;

#define LOAD_STAGE(s, kc)                                                          \
    {                                                                              \
        uint32_t sb = sbase + (s) * STAGEB;                                        \
        size_t gc = (size_t)(kc) * 64 + lq * 8;                                    \
        _Pragma("unroll")                                                          \
        for (int i = 0; i < 4; ++i) {                                              \
            int row = lrow + i * 32;                                               \
            uint32_t sf = (uint32_t)row * 128 + (((lq ^ (row & 7)) << 4));         \
            cpa16(sb + AHI + sf, hin_hi + (size_t)(m0 + row) * EDIM + gc);         \
            cpa16(sb + ALO + sf, hin_lo + (size_t)(m0 + row) * EDIM + gc);         \
        }                                                                          \
        _Pragma("unroll")                                                          \
        for (int i = 0; i < 8; ++i) {                                              \
            int row = lrow + i * 32;                                               \
            uint32_t sf = (uint32_t)row * 128 + (((lq ^ (row & 7)) << 4));         \
            cpa16(sb + BHI + sf, Bh + (size_t)(n0 + row) * EDIM + gc);             \
            cpa16(sb + BLO + sf, Bl + (size_t)(n0 + row) * EDIM + gc);             \
        }                                                                          \
        cpa_commit();                                                              \
    }

    // acc[mt][gate][sub][4] : m-tile mt (16 rows), gate, n8 sub-tile
    float acc[4][4][2][4];
#pragma unroll
    for (int i = 0; i < 4; ++i)
#pragma unroll
        for (int j = 0; j < 4; ++j)
#pragma unroll
            for (int s = 0; s < 2; ++s)
#pragma unroll
                for (int k = 0; k < 4; ++k) acc[i][j][s][k] = 0.f;

    // ldmatrix lane geometry
    const int arl = (lane & 7) + ((lane >> 3) & 1) * 8;   // A row within m16
    const int adq = lane >> 4;                            // A k-quad offset
    const int bn = (lane & 7) + ((lane >> 4) << 3);       // B n within n16
    const int bdq = (lane >> 3) & 1;                      // B k-quad offset

    LOAD_STAGE(0, 0)
    LOAD_STAGE(1, 1)

    for (int kc = 0; kc < NCK; ++kc) {
        if (kc == NCK - 1)
            asm volatile("cp.async.wait_group 0;" ::: "memory");
        else
            asm volatile("cp.async.wait_group 1;" ::: "memory");
        __syncthreads();
        uint32_t sb = sbase + (kc & 1) * STAGEB;
#pragma unroll
        for (int k16 = 0; k16 < 4; ++k16) {
            int qa = k16 * 2 + adq;
            int qb = k16 * 2 + bdq;
            uint32_t aoffs[4], boffs[4];
#pragma unroll
            for (int mt = 0; mt < 4; ++mt) {
                int ar = wr * 64 + mt * 16 + arl;
                aoffs[mt] = (uint32_t)ar * 128 + ((qa ^ (ar & 7)) << 4);
            }
#pragma unroll
            for (int g = 0; g < 4; ++g) {
                int br = g * 64 + wc * 16 + bn;
                boffs[g] = (uint32_t)br * 128 + ((qb ^ (br & 7)) << 4);
            }
            uint32_t ah[4][4], bhf[4][4];
#pragma unroll
            for (int mt = 0; mt < 4; ++mt) ldsm4(ah[mt], sb + AHI + aoffs[mt]);
#pragma unroll
            for (int g = 0; g < 4; ++g) ldsm4(bhf[g], sb + BHI + boffs[g]);
            // pass 1: hi*hi
#pragma unroll
            for (int mt = 0; mt < 4; ++mt)
#pragma unroll
                for (int g = 0; g < 4; ++g) {
                    mma16816(acc[mt][g][0], ah[mt], bhf[g][0], bhf[g][1]);
                    mma16816(acc[mt][g][1], ah[mt], bhf[g][2], bhf[g][3]);
                }
            // pass 2: hi*lo
            {
                uint32_t blf[4][4];
#pragma unroll
                for (int g = 0; g < 4; ++g) ldsm4(blf[g], sb + BLO + boffs[g]);
#pragma unroll
                for (int mt = 0; mt < 4; ++mt)
#pragma unroll
                    for (int g = 0; g < 4; ++g) {
                        mma16816(acc[mt][g][0], ah[mt], blf[g][0], blf[g][1]);
                        mma16816(acc[mt][g][1], ah[mt], blf[g][2], blf[g][3]);
                    }
            }
            // pass 3: lo*hi
            {
                uint32_t al[4][4];
#pragma unroll
                for (int mt = 0; mt < 4; ++mt) ldsm4(al[mt], sb + ALO + aoffs[mt]);
#pragma unroll
                for (int mt = 0; mt < 4; ++mt)
#pragma unroll
                    for (int g = 0; g < 4; ++g) {
                        mma16816(acc[mt][g][0], al[mt], bhf[g][0], bhf[g][1]);
                        mma16816(acc[mt][g][1], al[mt], bhf[g][2], bhf[g][3]);
                    }
            }
        }
        __syncthreads();
        if (kc + 2 < NCK) {
            LOAD_STAGE((kc & 1), kc + 2)
        }
    }

    // ---- fused epilogue: per-thread register LSTM update ----
    const int mbase = m0 + wr * 64 + (lane >> 2);
    const int cp2 = (lane & 3) * 2;
    float* hseq = g_hseq + (size_t)t * HSZ;
#pragma unroll
    for (int mt = 0; mt < 4; ++mt) {
#pragma unroll
        for (int rr = 0; rr < 2; ++rr) {
            int m = mbase + mt * 16 + rr * 8;
#pragma unroll
            for (int sub = 0; sub < 2; ++sub) {
                int el = wc * 16 + sub * 8 + cp2;
                float xi0 = acc[mt][0][sub][rr*2+0] + bias_sm[el];
                float xi1 = acc[mt][0][sub][rr*2+1] + bias_sm[el + 1];
                float xf0 = acc[mt][1][sub][rr*2+0] + bias_sm[64 + el];
                float xf1 = acc[mt][1][sub][rr*2+1] + bias_sm[64 + el + 1];
                float xg0 = acc[mt][2][sub][rr*2+0] + bias_sm[128 + el];
                float xg1 = acc[mt][2][sub][rr*2+1] + bias_sm[128 + el + 1];
                float xo0 = acc[mt][3][sub][rr*2+0] + bias_sm[192 + el];
                float xo1 = acc[mt][3][sub][rr*2+1] + bias_sm[192 + el + 1];
                size_t off = (size_t)m * EDIM + nb * 64 + el;
                float2 cold = *reinterpret_cast<const float2*>(g_c + off);
                float cn0 = fsig(xf0) * cold.x + fsig(xi0) * ftanh_(xg0);
                float cn1 = fsig(xf1) * cold.y + fsig(xi1) * ftanh_(xg1);
                float hn0 = fsig(xo0) * ftanh_(cn0);
                float hn1 = fsig(xo1) * ftanh_(cn1);
                *reinterpret_cast<float2*>(g_c + off) = make_float2(cn0, cn1);
                *reinterpret_cast<float2*>(hseq + off) = make_float2(hn0, hn1);
                unsigned short h0, l0, h1, l1;
                bsplit(hn0, h0, l0);
                bsplit(hn1, h1, l1);
                *reinterpret_cast<uint32_t*>(reinterpret_cast<unsigned short*>(hout_hi) + off) =
                    (uint32_t)h0 | ((uint32_t)h1 << 16);
                *reinterpret_cast<uint32_t*>(reinterpret_cast<unsigned short*>(hout_lo) + off) =
                    (uint32_t)l0 | ((uint32_t)l1 << 16);
            }
        }
    }
}

// ----------------- output projection -----------------
#define OPR 16
#define OPSTRIDE 1040
__global__ void out_proj(const float* __restrict__ Wo, const float* __restrict__ bo,
                         float* __restrict__ out, int T) {
    extern __shared__ float hs[];   // OPR rows, stride OPSTRIDE
    int t = blockIdx.y;
    int b0 = blockIdx.x * OPR;
    int tid = threadIdx.y * 17 + threadIdx.x;   // 136 threads
    const float4* src = reinterpret_cast<const float4*>(g_hseq + ((size_t)t * BDIM + b0) * EDIM);
    for (int i = tid; i < OPR * 256; i += 136) {
        int r = i >> 8, c = i & 255;
        reinterpret_cast<float4*>(hs + r * OPSTRIDE)[c] = src[(size_t)r * 256 + c];
    }
    __syncthreads();
    int o0 = threadIdx.x * 2, o1 = o0 + 1;
    int r0 = threadIdx.y * 2, r1 = r0 + 1;
    const float4* w0 = reinterpret_cast<const float4*>(Wo + (size_t)o0 * EDIM);
    const float4* w1 = reinterpret_cast<const float4*>(Wo + (size_t)o1 * EDIM);
    const float4* h0 = reinterpret_cast<const float4*>(hs + r0 * OPSTRIDE);
    const float4* h1 = reinterpret_cast<const float4*>(hs + r1 * OPSTRIDE);
    float s00 = 0.f, s01 = 0.f, s10 = 0.f, s11 = 0.f;
#pragma unroll 4
    for (int k = 0; k < 256; ++k) {
        float4 a = h0[k], b = h1[k], x = w0[k], y = w1[k];
        s00 += a.x * x.x + a.y * x.y + a.z * x.z + a.w * x.w;
        s01 += a.x * y.x + a.y * y.y + a.z * y.z + a.w * y.w;
        s10 += b.x * x.x + b.y * x.y + b.z * x.z + b.w * x.w;
        s11 += b.x * y.x + b.y * y.y + b.z * y.z + b.w * y.w;
    }
    float bb0 = bo[o0], bb1 = bo[o1];
    size_t ob = ((size_t)(b0 + r0) * T + t) * OUTD;
    out[ob + o0] = s00 + bb0;
    out[ob + o1] = s01 + bb1;
    ob = ((size_t)(b0 + r1) * T + t) * OUTD;
    out[ob + o0] = s10 + bb0;
    out[ob + o1] = s11 + bb1;
}

// ----------------- launch -----------------
extern "C" void kernel_launch(void* const* d_in, const int* in_sizes, int n_in,
                              void* d_out, int out_size) {
    const float* h     = (const float*)d_in[0];
    const float* c     = (const float*)d_in[1];
    const float* W_ih  = (const float*)d_in[2];
    const float* W_hh  = (const float*)d_in[3];
    const float* b_ih  = (const float*)d_in[4];
    const float* b_hh  = (const float*)d_in[5];
    const float* W_out = (const float*)d_in[6];
    const float* b_out = (const float*)d_in[7];
    float* out = (float*)d_out;

    int T = out_size / (BDIM * OUTD);
    if (T < 1) T = 1;
    if (T > MAXT) T = MAXT;

    cudaFuncSetAttribute(lstm_step, cudaFuncAttributeMaxDynamicSharedMemorySize, SMEM_LSTM);
    cudaFuncSetAttribute(out_proj, cudaFuncAttributeMaxDynamicSharedMemorySize,
                         OPR * OPSTRIDE * 4);

    prep_w<<<G4, 256>>>(W_ih, W_hh);
    prep_state<<<(BDIM * EDIM / 4) / 256, 256>>>(h, c, b_ih, b_hh);

    dim3 grid(G4 / BN, BDIM / BM);   // (16, 8) = 128 CTAs = 1 wave
    for (int t = 0; t < T; ++t)
        lstm_step<<<grid, NTHREADS, SMEM_LSTM>>>(t > 0 ? 1 : 0, t);

    dim3 opgrid(BDIM / OPR, T);
    dim3 opblk(17, 8);
    out_proj<<<opgrid, opblk, OPR * OPSTRIDE * 4>>>(W_out, b_out, out, T);
}

// round 7
// speedup vs baseline: 3.0683x; 1.0017x over previous
#include <cuda_runtime.h>
#include <cuda_bf16.h>
#include <cstdint>

#define EDIM 1024
#define BDIM 1024
#define G4   4096
#define MAXT 16
#define OUTD 34

#define BM 128
#define BN 256
#define BK 64
#define NCK (EDIM / BK)        // 16 k-chunks
#define NTHREADS 512

#define STAGEB 98304           // Ahi16K + Alo16K + Bhi32K + Blo32K
#define AHI 0
#define ALO 16384
#define BHI 32768
#define BLO 65536
#define SMEM_LSTM (1024 + 2 * STAGEB)   // bias + 2 stages = 197632

#define HSZ (BDIM * EDIM)

// ----------------- device scratch -----------------
__device__ __nv_bfloat16 g_Ws_hi[G4 * EDIM];
__device__ __nv_bfloat16 g_Ws_lo[G4 * EDIM];
__device__ __nv_bfloat16 g_Wh_hi[G4 * EDIM];
__device__ __nv_bfloat16 g_Wh_lo[G4 * EDIM];
__device__ float         g_bsum_p[G4];
// ping-pong h buffers: step t reads parity t&1, writes parity (t+1)&1.
__device__ __nv_bfloat16 g_hhi[2 * HSZ];
__device__ __nv_bfloat16 g_hlo[2 * HSZ];
__device__ float         g_c[HSZ];
__device__ float         g_hseq[MAXT * HSZ];

// ----------------- helpers -----------------
__device__ __forceinline__ uint32_t smem_u32(const void* p) {
    uint32_t a;
    asm("{ .reg .u64 t; cvta.to.shared.u64 t, %1; cvt.u32.u64 %0, t; }" : "=r"(a) : "l"(p));
    return a;
}
__device__ __forceinline__ void cpa16(uint32_t dst, const void* src) {
    asm volatile("cp.async.cg.shared.global [%0], [%1], 16;" :: "r"(dst), "l"(src));
}
__device__ __forceinline__ void cpa_commit() {
    asm volatile("cp.async.commit_group;" ::: "memory");
}
__device__ __forceinline__ void ldsm4(uint32_t* r, uint32_t a) {
    asm volatile("ldmatrix.sync.aligned.m8n8.x4.shared.b16 {%0,%1,%2,%3}, [%4];"
                 : "=r"(r[0]), "=r"(r[1]), "=r"(r[2]), "=r"(r[3]) : "r"(a));
}
__device__ __forceinline__ void mma16816(float* d,
                                         const uint32_t* a,
                                         uint32_t b0, uint32_t b1) {
    asm volatile("mma.sync.aligned.m16n8k16.row.col.f32.bf16.bf16.f32 "
                 "{%0,%1,%2,%3}, {%4,%5,%6,%7}, {%8,%9}, {%0,%1,%2,%3};"
                 : "+f"(d[0]), "+f"(d[1]), "+f"(d[2]), "+f"(d[3])
                 : "r"(a[0]), "r"(a[1]), "r"(a[2]), "r"(a[3]), "r"(b0), "r"(b1));
}
__device__ __forceinline__ float fsig(float x) {
    float t = __expf(-x);
    return __fdividef(1.f, 1.f + t);
}
__device__ __forceinline__ float ftanh_(float x) {
    float t = __expf(-2.f * x);
    return __fdividef(1.f - t, 1.f + t);
}
__device__ __forceinline__ void bsplit(float v, unsigned short& h, unsigned short& l) {
    __nv_bfloat16 hb = __float2bfloat16(v);
    float r = v - __bfloat162float(hb);
    __nv_bfloat16 lb = __float2bfloat16(r);
    h = __bfloat16_as_ushort(hb);
    l = __bfloat16_as_ushort(lb);
}

// permutation: original W row r = g*1024 + e  ->  rp = (e>>6)*256 + g*64 + (e&63)
// so N-block nb (256 rows) holds e in [nb*64, nb*64+64) for all 4 gates,
// gate g at local rows [g*64, g*64+64).

// ----------------- prep kernels -----------------
__global__ void prep_w(const float* __restrict__ Wih, const float* __restrict__ Whh) {
    int id = blockIdx.x * 256 + threadIdx.x;     // row * 256 float4 quads
    int r = id >> 8;
    int q = id & 255;
    float4 a = reinterpret_cast<const float4*>(Wih)[(size_t)r * 256 + q];
    float4 b = reinterpret_cast<const float4*>(Whh)[(size_t)r * 256 + q];
    int g = r >> 10, e = r & 1023;
    int rp = ((e >> 6) << 8) + (g << 6) + (e & 63);
    size_t o = (size_t)rp * 256 + q;

    ushort4 hh, hl, sh, sl;
    bsplit(b.x, hh.x, hl.x); bsplit(b.y, hh.y, hl.y);
    bsplit(b.z, hh.z, hl.z); bsplit(b.w, hh.w, hl.w);
    float4 s = make_float4(a.x + b.x, a.y + b.y, a.z + b.z, a.w + b.w);
    bsplit(s.x, sh.x, sl.x); bsplit(s.y, sh.y, sl.y);
    bsplit(s.z, sh.z, sl.z); bsplit(s.w, sh.w, sl.w);

    reinterpret_cast<ushort4*>(g_Wh_hi)[o] = hh;
    reinterpret_cast<ushort4*>(g_Wh_lo)[o] = hl;
    reinterpret_cast<ushort4*>(g_Ws_hi)[o] = sh;
    reinterpret_cast<ushort4*>(g_Ws_lo)[o] = sl;
}

__global__ void prep_state(const float* __restrict__ h0, const float* __restrict__ c0,
                           const float* __restrict__ bih, const float* __restrict__ bhh) {
    int id = blockIdx.x * 256 + threadIdx.x;     // float4 index over B*E/4
    float4 hv = reinterpret_cast<const float4*>(h0)[id];
    ushort4 hh, hl;
    bsplit(hv.x, hh.x, hl.x); bsplit(hv.y, hh.y, hl.y);
    bsplit(hv.z, hh.z, hl.z); bsplit(hv.w, hh.w, hl.w);
    reinterpret_cast<ushort4*>(g_hhi)[id] = hh;   // parity-0 buffer
    reinterpret_cast<ushort4*>(g_hlo)[id] = hl;
    reinterpret_cast<float4*>(g_c)[id] = reinterpret_cast<const float4*>(c0)[id];
    if (id < G4) {
        int g = id >> 10, e = id & 1023;
        int rp = ((e >> 6) << 8) + (g << 6) + (e & 63);
        g_bsum_p[rp] = bih[id] + bhh[id];
    }
}

// ----------------- fused GEMM (mma.sync bf16 3-term) + LSTM update -----------------
__global__ __launch_bounds__(NTHREADS, 1)
void lstm_step(int use_sum, int t) {
    extern __shared__ char smem[];
    float* bias_sm = reinterpret_cast<float*>(smem);
    const uint32_t sbase = smem_u32(smem) + 1024;
    const int tid = threadIdx.x;
    const int lane = tid & 31;
    const int w = tid >> 5;        // 0..15
    const int wm = w & 3;          // m-group (32 rows)
    const int we = w >> 2;         // e-group (16 e-cols)
    const int nb = blockIdx.x;     // 0..15
    const int mb = blockIdx.y;     // 0..7
    const int m0 = mb * BM, n0 = nb * BN;

    // ping-pong: read parity t&1, write parity (t+1)&1
    const __nv_bfloat16* __restrict__ hin_hi = g_hhi + (size_t)(t & 1) * HSZ;
    const __nv_bfloat16* __restrict__ hin_lo = g_hlo + (size_t)(t & 1) * HSZ;
    __nv_bfloat16* __restrict__ hout_hi = g_hhi + (size_t)((t + 1) & 1) * HSZ;
    __nv_bfloat16* __restrict__ hout_lo = g_hlo + (size_t)((t + 1) & 1) * HSZ;

    const __nv_bfloat16* __restrict__ Bh = use_sum ? g_Ws_hi : g_Wh_hi;
    const __nv_bfloat16* __restrict__ Bl = use_sum ? g_Ws_lo : g_Wh_lo;

    if (tid < BN) bias_sm[tid] = g_bsum_p[n0 + tid];

    // ---- loaders: 12 cp.async per thread per stage (512 threads) ----
    const int lrow = tid >> 3;     // 0..63
    const int lq = tid & 7;

#define LOAD_STAGE(s, kc)                                                          \
    {                                                                              \
        uint32_t sb = sbase + (s) * STAGEB;                                        \
        size_t gc = (size_t)(kc) * 64 + lq * 8;                                    \
        _Pragma("unroll")                                                          \
        for (int i = 0; i < 2; ++i) {                                              \
            int row = lrow + i * 64;                                               \
            uint32_t sf = (uint32_t)row * 128 + (((lq ^ (row & 7)) << 4));         \
            cpa16(sb + AHI + sf, hin_hi + (size_t)(m0 + row) * EDIM + gc);         \
            cpa16(sb + ALO + sf, hin_lo + (size_t)(m0 + row) * EDIM + gc);         \
        }                                                                          \
        _Pragma("unroll")                                                          \
        for (int i = 0; i < 4; ++i) {                                              \
            int row = lrow + i * 64;                                               \
            uint32_t sf = (uint32_t)row * 128 + (((lq ^ (row & 7)) << 4));         \
            cpa16(sb + BHI + sf, Bh + (size_t)(n0 + row) * EDIM + gc);             \
            cpa16(sb + BLO + sf, Bl + (size_t)(n0 + row) * EDIM + gc);             \
        }                                                                          \
        cpa_commit();                                                              \
    }

    // acc[mt][gate][sub][4] : m-tile mt (16 rows), gate, n8 sub-tile
    float acc[2][4][2][4];
#pragma unroll
    for (int i = 0; i < 2; ++i)
#pragma unroll
        for (int j = 0; j < 4; ++j)
#pragma unroll
            for (int s = 0; s < 2; ++s)
#pragma unroll
                for (int k = 0; k < 4; ++k) acc[i][j][s][k] = 0.f;

    // ldmatrix lane geometry
    const int arl = (lane & 7) + ((lane >> 3) & 1) * 8;   // A row within m16
    const int adq = lane >> 4;                            // A k-quad offset
    const int bn = (lane & 7) + ((lane >> 4) << 3);       // B n within n16
    const int bdq = (lane >> 3) & 1;                      // B k-quad offset

    LOAD_STAGE(0, 0)
    LOAD_STAGE(1, 1)

    for (int kc = 0; kc < NCK; ++kc) {
        if (kc == NCK - 1)
            asm volatile("cp.async.wait_group 0;" ::: "memory");
        else
            asm volatile("cp.async.wait_group 1;" ::: "memory");
        __syncthreads();
        uint32_t sb = sbase + (kc & 1) * STAGEB;
#pragma unroll
        for (int k16 = 0; k16 < 4; ++k16) {
            int qa = k16 * 2 + adq;
            int qb = k16 * 2 + bdq;
            uint32_t aoffs[2], boffs[4];
#pragma unroll
            for (int mt = 0; mt < 2; ++mt) {
                int ar = wm * 32 + mt * 16 + arl;
                aoffs[mt] = (uint32_t)ar * 128 + ((qa ^ (ar & 7)) << 4);
            }
#pragma unroll
            for (int g = 0; g < 4; ++g) {
                int br = g * 64 + we * 16 + bn;
                boffs[g] = (uint32_t)br * 128 + ((qb ^ (br & 7)) << 4);
            }
            uint32_t ah[2][4], bf[4][4];
#pragma unroll
            for (int mt = 0; mt < 2; ++mt) ldsm4(ah[mt], sb + AHI + aoffs[mt]);
#pragma unroll
            for (int g = 0; g < 4; ++g) ldsm4(bf[g], sb + BHI + boffs[g]);
            // pass 1: hi*hi
#pragma unroll
            for (int mt = 0; mt < 2; ++mt)
#pragma unroll
                for (int g = 0; g < 4; ++g) {
                    mma16816(acc[mt][g][0], ah[mt], bf[g][0], bf[g][1]);
                    mma16816(acc[mt][g][1], ah[mt], bf[g][2], bf[g][3]);
                }
            // pass 2: lo*hi (al live only here)
            {
                uint32_t al[2][4];
#pragma unroll
                for (int mt = 0; mt < 2; ++mt) ldsm4(al[mt], sb + ALO + aoffs[mt]);
#pragma unroll
                for (int mt = 0; mt < 2; ++mt)
#pragma unroll
                    for (int g = 0; g < 4; ++g) {
                        mma16816(acc[mt][g][0], al[mt], bf[g][0], bf[g][1]);
                        mma16816(acc[mt][g][1], al[mt], bf[g][2], bf[g][3]);
                    }
            }
            // pass 3: hi*lo (reuse bf registers for BLO fragments)
#pragma unroll
            for (int g = 0; g < 4; ++g) ldsm4(bf[g], sb + BLO + boffs[g]);
#pragma unroll
            for (int mt = 0; mt < 2; ++mt)
#pragma unroll
                for (int g = 0; g < 4; ++g) {
                    mma16816(acc[mt][g][0], ah[mt], bf[g][0], bf[g][1]);
                    mma16816(acc[mt][g][1], ah[mt], bf[g][2], bf[g][3]);
                }
        }
        __syncthreads();
        if (kc + 2 < NCK) {
            LOAD_STAGE((kc & 1), kc + 2)
        }
    }

    // ---- fused epilogue: per-thread register LSTM update ----
    const int mbase = m0 + wm * 32 + (lane >> 2);
    const int cp2 = (lane & 3) * 2;
    float* hseq = g_hseq + (size_t)t * HSZ;
#pragma unroll
    for (int mt = 0; mt < 2; ++mt) {
#pragma unroll
        for (int rr = 0; rr < 2; ++rr) {
            int m = mbase + mt * 16 + rr * 8;
#pragma unroll
            for (int sub = 0; sub < 2; ++sub) {
                int el = we * 16 + sub * 8 + cp2;
                float xi0 = acc[mt][0][sub][rr*2+0] + bias_sm[el];
                float xi1 = acc[mt][0][sub][rr*2+1] + bias_sm[el + 1];
                float xf0 = acc[mt][1][sub][rr*2+0] + bias_sm[64 + el];
                float xf1 = acc[mt][1][sub][rr*2+1] + bias_sm[64 + el + 1];
                float xg0 = acc[mt][2][sub][rr*2+0] + bias_sm[128 + el];
                float xg1 = acc[mt][2][sub][rr*2+1] + bias_sm[128 + el + 1];
                float xo0 = acc[mt][3][sub][rr*2+0] + bias_sm[192 + el];
                float xo1 = acc[mt][3][sub][rr*2+1] + bias_sm[192 + el + 1];
                size_t off = (size_t)m * EDIM + nb * 64 + el;
                float2 cold = *reinterpret_cast<const float2*>(g_c + off);
                float cn0 = fsig(xf0) * cold.x + fsig(xi0) * ftanh_(xg0);
                float cn1 = fsig(xf1) * cold.y + fsig(xi1) * ftanh_(xg1);
                float hn0 = fsig(xo0) * ftanh_(cn0);
                float hn1 = fsig(xo1) * ftanh_(cn1);
                *reinterpret_cast<float2*>(g_c + off) = make_float2(cn0, cn1);
                *reinterpret_cast<float2*>(hseq + off) = make_float2(hn0, hn1);
                unsigned short h0, l0, h1, l1;
                bsplit(hn0, h0, l0);
                bsplit(hn1, h1, l1);
                *reinterpret_cast<uint32_t*>(reinterpret_cast<unsigned short*>(hout_hi) + off) =
                    (uint32_t)h0 | ((uint32_t)h1 << 16);
                *reinterpret_cast<uint32_t*>(reinterpret_cast<unsigned short*>(hout_lo) + off) =
                    (uint32_t)l0 | ((uint32_t)l1 << 16);
            }
        }
    }
}

// ----------------- output projection -----------------
#define OPR 16
#define OPSTRIDE 1040
__global__ void out_proj(const float* __restrict__ Wo, const float* __restrict__ bo,
                         float* __restrict__ out, int T) {
    extern __shared__ float hs[];   // OPR rows, stride OPSTRIDE
    int t = blockIdx.y;
    int b0 = blockIdx.x * OPR;
    int tid = threadIdx.y * 17 + threadIdx.x;   // 136 threads
    const float4* src = reinterpret_cast<const float4*>(g_hseq + ((size_t)t * BDIM + b0) * EDIM);
    for (int i = tid; i < OPR * 256; i += 136) {
        int r = i >> 8, c = i & 255;
        reinterpret_cast<float4*>(hs + r * OPSTRIDE)[c] = src[(size_t)r * 256 + c];
    }
    __syncthreads();
    int o0 = threadIdx.x * 2, o1 = o0 + 1;
    int r0 = threadIdx.y * 2, r1 = r0 + 1;
    const float4* w0 = reinterpret_cast<const float4*>(Wo + (size_t)o0 * EDIM);
    const float4* w1 = reinterpret_cast<const float4*>(Wo + (size_t)o1 * EDIM);
    const float4* h0 = reinterpret_cast<const float4*>(hs + r0 * OPSTRIDE);
    const float4* h1 = reinterpret_cast<const float4*>(hs + r1 * OPSTRIDE);
    float s00 = 0.f, s01 = 0.f, s10 = 0.f, s11 = 0.f;
#pragma unroll 4
    for (int k = 0; k < 256; ++k) {
        float4 a = h0[k], b = h1[k], x = w0[k], y = w1[k];
        s00 += a.x * x.x + a.y * x.y + a.z * x.z + a.w * x.w;
        s01 += a.x * y.x + a.y * y.y + a.z * y.z + a.w * y.w;
        s10 += b.x * x.x + b.y * x.y + b.z * x.z + b.w * x.w;
        s11 += b.x * y.x + b.y * y.y + b.z * y.z + b.w * y.w;
    }
    float bb0 = bo[o0], bb1 = bo[o1];
    size_t ob = ((size_t)(b0 + r0) * T + t) * OUTD;
    out[ob + o0] = s00 + bb0;
    out[ob + o1] = s01 + bb1;
    ob = ((size_t)(b0 + r1) * T + t) * OUTD;
    out[ob + o0] = s10 + bb0;
    out[ob + o1] = s11 + bb1;
}

// ----------------- launch -----------------
extern "C" void kernel_launch(void* const* d_in, const int* in_sizes, int n_in,
                              void* d_out, int out_size) {
    const float* h     = (const float*)d_in[0];
    const float* c     = (const float*)d_in[1];
    const float* W_ih  = (const float*)d_in[2];
    const float* W_hh  = (const float*)d_in[3];
    const float* b_ih  = (const float*)d_in[4];
    const float* b_hh  = (const float*)d_in[5];
    const float* W_out = (const float*)d_in[6];
    const float* b_out = (const float*)d_in[7];
    float* out = (float*)d_out;

    int T = out_size / (BDIM * OUTD);
    if (T < 1) T = 1;
    if (T > MAXT) T = MAXT;

    cudaFuncSetAttribute(lstm_step, cudaFuncAttributeMaxDynamicSharedMemorySize, SMEM_LSTM);
    cudaFuncSetAttribute(out_proj, cudaFuncAttributeMaxDynamicSharedMemorySize,
                         OPR * OPSTRIDE * 4);

    prep_w<<<G4, 256>>>(W_ih, W_hh);
    prep_state<<<(BDIM * EDIM / 4) / 256, 256>>>(h, c, b_ih, b_hh);

    dim3 grid(G4 / BN, BDIM / BM);   // (16, 8) = 128 CTAs = 1 wave
    for (int t = 0; t < T; ++t)
        lstm_step<<<grid, NTHREADS, SMEM_LSTM>>>(t > 0 ? 1 : 0, t);

    dim3 opgrid(BDIM / OPR, T);
    dim3 opblk(17, 8);
    out_proj<<<opgrid, opblk, OPR * OPSTRIDE * 4>>>(W_out, b_out, out, T);
}